// round 9
// baseline (speedup 1.0000x reference)
#include <cuda_runtime.h>
#include <math.h>

#define NT 2000
#define NPT 255
#define NC 16
#define NM 32
#define NG 16
#define PGRID 296                     // persistent grid: 2 CTAs/SM x 148 SMs
#define NPAIR (NT/2)

typedef unsigned long long ull;

// dynamic shared layout (float offsets)
#define WSLOT_FLOATS (32*256)         // per-tree in-place pairsum region (32KB)
#define PB_OFF   (2*WSLOT_FLOATS)     // normalized leaf beta Pi*B/nu, [m][g][c]
#define NUL_OFF  (PB_OFF + NM*NG*NC)  // log2 nu per (m,g)
#define DYN_FLOATS (NUL_OFF + NM*NG)
#define DYN_BYTES  (DYN_FLOATS*4)     // 65536+32768+2048 = 100352 B -> 2 CTAs/SM

__device__ float g_smA[NC*NC*NG];     // softmaxed A, [p][c][g]
__device__ float g_smBf[NM*NG*NC];    // softmaxed B, [m][g][c] (prologue scratch)
__device__ float g_smPi[NC*NG];       // softmaxed Pi, [c][g]
__device__ float g_PiBn[NM*NG*NC];    // normalized leaf beta, [m][g][c]
__device__ float g_nuLog[NM*NG];      // log2 nu per (m,g)

// ---------------------------------------------------------------------------
// packed f32x2 helpers (FFMA2/FADD2 only reachable via PTX)
// ---------------------------------------------------------------------------
__device__ __forceinline__ ull pack2(float lo, float hi) {
    ull r; asm("mov.b64 %0, {%1, %2};" : "=l"(r) : "f"(lo), "f"(hi)); return r;
}
__device__ __forceinline__ void ffma2(ull& d, ull a, ull b) {
    asm("fma.rn.f32x2 %0, %1, %2, %0;" : "+l"(d) : "l"(a), "l"(b));
}
__device__ __forceinline__ void fadd2(ull& d, ull a) {
    asm("add.rn.f32x2 %0, %0, %1;" : "+l"(d) : "l"(a));
}
__device__ __forceinline__ float unpack_sum(ull v) {
    float lo, hi; asm("mov.b64 {%0, %1}, %2;" : "=f"(lo), "=f"(hi) : "l"(v));
    return lo + hi;
}

// ---------------------------------------------------------------------------
// Prologue: softmaxes + normalized leaf table + log2 nu. 1 block, 256 thr.
// ---------------------------------------------------------------------------
__global__ void htmm_softmax_kernel(const float* __restrict__ A,
                                    const float* __restrict__ B,
                                    const float* __restrict__ Pi) {
    int tid = threadIdx.x;
    int c = tid >> 4;
    int g = tid & 15;
    {   // A: softmax over p for each (c,g)
        float mx = -1e30f;
        #pragma unroll
        for (int p = 0; p < NC; p++) mx = fmaxf(mx, A[p*NC*NG + c*NG + g]);
        float e[NC]; float s = 0.f;
        #pragma unroll
        for (int p = 0; p < NC; p++) { e[p] = expf(A[p*NC*NG + c*NG + g] - mx); s += e[p]; }
        float rs = 1.f / s;
        #pragma unroll
        for (int p = 0; p < NC; p++) g_smA[p*NC*NG + c*NG + g] = e[p] * rs;
    }
    {   // B: softmax over m for each (c,g); store [m][g][c]
        float mx = -1e30f;
        #pragma unroll
        for (int m = 0; m < NM; m++) mx = fmaxf(mx, B[c*NM*NG + m*NG + g]);
        float s = 0.f;
        #pragma unroll
        for (int m = 0; m < NM; m++) s += expf(B[c*NM*NG + m*NG + g] - mx);
        float rs = 1.f / s;
        #pragma unroll
        for (int m = 0; m < NM; m++)
            g_smBf[m*NG*NC + g*NC + c] = expf(B[c*NM*NG + m*NG + g] - mx) * rs;
    }
    if (tid < NG) {   // Pi: softmax over c for each g
        int gg = tid;
        float mx = -1e30f;
        #pragma unroll
        for (int cc = 0; cc < NC; cc++) mx = fmaxf(mx, Pi[cc*NG + gg]);
        float s = 0.f;
        #pragma unroll
        for (int cc = 0; cc < NC; cc++) s += expf(Pi[cc*NG + gg] - mx);
        float rs = 1.f / s;
        #pragma unroll
        for (int cc = 0; cc < NC; cc++)
            g_smPi[cc*NG + gg] = expf(Pi[cc*NG + gg] - mx) * rs;
    }
    __syncthreads();
    // per (m,g): v = Pi*B; nu = sum v; PiBn = v/nu; log2 nu
    for (int i = tid; i < NM*NG; i += 256) {
        int m = i >> 4, gg = i & 15;
        float v[NC]; float nu = 0.f;
        #pragma unroll
        for (int cc = 0; cc < NC; cc++) {
            v[cc] = g_smPi[cc*NG + gg] * g_smBf[m*NG*NC + gg*NC + cc];
            nu += v[cc];
        }
        float rnu = 1.f / nu;
        #pragma unroll
        for (int cc = 0; cc < NC; cc++)
            g_PiBn[m*NG*NC + gg*NC + cc] = v[cc] * rnu;
        g_nuLog[i] = log2f(nu);
    }
}

// ---------------------------------------------------------------------------
// Main kernel: PERSISTENT over tree PAIRS — two independent trees interleaved
// per thread for 2x ILP on the latency chains. Emission reconstructed from
// the normalized leaf table: B[c] = PB[mu][c] * invPi[c] * nu(mu); nu cancels
// in normalization and contributes +log2 nu(mu) to ll (table lookup).
// pblk = tid&3 (states p = 4*pblk..+3), g = (tid>>2)&15, ng = tid>>6.
// ---------------------------------------------------------------------------
__global__ void __launch_bounds__(256, 2)
htmm_upward_kernel(const int* __restrict__ x, float* __restrict__ out) {
    extern __shared__ __align__(16) float sm[];
    float* sW0  = sm;                  // tree-0 pairsum slots (in-place doubling)
    float* sW1  = sm + WSLOT_FLOATS;   // tree-1 pairsum slots
    float* sPB  = sm + PB_OFF;         // [m][g][c]
    float* sNuL = sm + NUL_OFF;        // [m*NG+g] log2 nu
    __shared__ int   sx0[NPT], sx1[NPT];
    __shared__ float sacc0[256], sacc1[256];

    const int tid  = threadIdx.x;
    const int pblk = tid & 3;
    const int g    = (tid >> 2) & 15;
    const int ng   = tid >> 6;

    // ---- stage tables ONCE (A via sW0 scratch; consumed into regs) ----
    for (int i = tid; i < NC*NC*NG; i += 256)  sW0[i] = g_smA[i];
    for (int i = tid; i < NM*NG*NC; i += 256)  sPB[i] = g_PiBn[i];
    for (int i = tid; i < NM*NG; i += 256)     sNuL[i] = g_nuLog[i];
    __syncthreads();

    // A packed along c-pairs for this thread's states p = 4*pblk+ip
    ull A2[4][8];
    #pragma unroll
    for (int ip = 0; ip < 4; ip++) {
        int p = 4*pblk + ip;
        #pragma unroll
        for (int c2 = 0; c2 < 8; c2++)
            A2[ip][c2] = pack2(sW0[p*256 + (2*c2)*16 + g],
                               sW0[p*256 + (2*c2+1)*16 + g]);
    }
    // reciprocal Pi for this thread's 4 states (emission reconstruction)
    float invPi0 = 1.f / g_smPi[(4*pblk+0)*NG + g];
    float invPi1 = 1.f / g_smPi[(4*pblk+1)*NG + g];
    float invPi2 = 1.f / g_smPi[(4*pblk+2)*NG + g];
    float invPi3 = 1.f / g_smPi[(4*pblk+3)*NG + g];

    // ---- persistent pair loop ----
    for (int pair = blockIdx.x; pair < NPAIR; pair += PGRID) {
        __syncthreads();   // protect sW/sx reuse
        for (int i = tid; i < NPT; i += 256) {
            sx0[i] = x[(2*pair    )*NPT + i];
            sx1[i] = x[(2*pair + 1)*NPT + i];
        }
        __syncthreads();

        float accll[2] = {0.f, 0.f};   // log2 units

        // ---- Level 6 (leaves fused): parents k in [0,32) -> slot k ----
        for (int k = ng; k < 32; k += 4) {
            #pragma unroll
            for (int t = 0; t < 2; t++) {
                float* sWt = t ? sW1 : sW0;
                const int* sxt = t ? sx1 : sx0;
                float wo0 = 0.f, wo1 = 0.f, wo2 = 0.f, wo3 = 0.f;
                #pragma unroll
                for (int sel = 0; sel < 2; sel++) {
                    const int j  = 2*k + sel;
                    const int m0 = sxt[127 + 2*j], m1 = sxt[128 + 2*j];
                    const ull* b0 = (const ull*)(sPB + m0*256 + g*16);
                    const ull* b1 = (const ull*)(sPB + m1*256 + g*16);
                    ull a0 = 0ull, a1 = 0ull, a2 = 0ull, a3 = 0ull;
                    #pragma unroll
                    for (int c2 = 0; c2 < 8; c2++) {
                        ull w = b0[c2];
                        fadd2(w, b1[c2]);        // beta_leaf0 + beta_leaf1
                        ffma2(a0, A2[0][c2], w);
                        ffma2(a1, A2[1][c2], w);
                        ffma2(a2, A2[2][c2], w);
                        ffma2(a3, A2[3][c2], w);
                    }
                    accll[t] += 0.25f * (sNuL[m0*NG + g] + sNuL[m1*NG + g]);

                    const int mu = sxt[63 + j];
                    const float4 e4 = *(const float4*)(sPB + mu*256 + g*16 + 4*pblk);
                    float bv0 = (e4.x*invPi0) * unpack_sum(a0);
                    float bv1 = (e4.y*invPi1) * unpack_sum(a1);
                    float bv2 = (e4.z*invPi2) * unpack_sum(a2);
                    float bv3 = (e4.w*invPi3) * unpack_sum(a3);
                    float s = (bv0 + bv1) + (bv2 + bv3);
                    s += __shfl_xor_sync(0xffffffffu, s, 1);
                    s += __shfl_xor_sync(0xffffffffu, s, 2);
                    float rs = __fdividef(1.f, s);
                    wo0 += bv0*rs; wo1 += bv1*rs; wo2 += bv2*rs; wo3 += bv3*rs;
                    accll[t] += 0.25f * (__log2f(s) + sNuL[mu*NG + g]);
                }
                *(float4*)(sWt + k*256 + g*16 + 4*pblk) =
                    make_float4(wo0, wo1, wo2, wo3);
            }
        }
        __syncthreads();

        // ---- Levels 5..1 (in-place, stride doubling) ----
        #pragma unroll 1
        for (int l = 5; l >= 1; l--) {
            const int nPar   = 1 << (l - 1);
            const int st     = 1 << (5 - l);        // input slot stride
            const int lstart = (1 << l) - 1;
            for (int k = ng; k < nPar; k += 4) {
                #pragma unroll
                for (int t = 0; t < 2; t++) {
                    float* sWt = t ? sW1 : sW0;
                    const int* sxt = t ? sx1 : sx0;
                    float wo0 = 0.f, wo1 = 0.f, wo2 = 0.f, wo3 = 0.f;
                    #pragma unroll
                    for (int sel = 0; sel < 2; sel++) {
                        const int j = 2*k + sel;
                        const ull* wv = (const ull*)(sWt + j*st*256 + g*16);
                        ull a0 = 0ull, a1 = 0ull, a2 = 0ull, a3 = 0ull;
                        #pragma unroll
                        for (int c2 = 0; c2 < 8; c2++) {
                            ull w = wv[c2];          // pre-summed sibling pair
                            ffma2(a0, A2[0][c2], w);
                            ffma2(a1, A2[1][c2], w);
                            ffma2(a2, A2[2][c2], w);
                            ffma2(a3, A2[3][c2], w);
                        }
                        const int mu = sxt[lstart + j];
                        const float4 e4 = *(const float4*)(sPB + mu*256 + g*16 + 4*pblk);
                        float bv0 = (e4.x*invPi0) * unpack_sum(a0);
                        float bv1 = (e4.y*invPi1) * unpack_sum(a1);
                        float bv2 = (e4.z*invPi2) * unpack_sum(a2);
                        float bv3 = (e4.w*invPi3) * unpack_sum(a3);
                        float s = (bv0 + bv1) + (bv2 + bv3);
                        s += __shfl_xor_sync(0xffffffffu, s, 1);
                        s += __shfl_xor_sync(0xffffffffu, s, 2);
                        // true nu scale: /2 and nu(mu) cancel in normalization;
                        // -1 folded at end, +log2 nu(mu) added here
                        float rs = __fdividef(1.f, s);
                        wo0 += bv0*rs; wo1 += bv1*rs; wo2 += bv2*rs; wo3 += bv3*rs;
                        accll[t] += 0.25f * (__log2f(s) + sNuL[mu*NG + g]);
                    }
                    *(float4*)(sWt + 2*k*st*256 + g*16 + 4*pblk) =
                        make_float4(wo0, wo1, wo2, wo3);
                }
            }
            __syncthreads();
        }

        // ---- Root (level 0): group 0 only; level 1 wrote slot 0 ----
        if (ng == 0) {
            #pragma unroll
            for (int t = 0; t < 2; t++) {
                float* sWt = t ? sW1 : sW0;
                const int* sxt = t ? sx1 : sx0;
                const ull* wv = (const ull*)(sWt + g*16);
                ull a0 = 0ull, a1 = 0ull, a2 = 0ull, a3 = 0ull;
                #pragma unroll
                for (int c2 = 0; c2 < 8; c2++) {
                    ull w = wv[c2];
                    ffma2(a0, A2[0][c2], w);
                    ffma2(a1, A2[1][c2], w);
                    ffma2(a2, A2[2][c2], w);
                    ffma2(a3, A2[3][c2], w);
                }
                const int mu = sxt[0];
                const float4 e4 = *(const float4*)(sPB + mu*256 + g*16 + 4*pblk);
                float s = ((e4.x*invPi0)*unpack_sum(a0) + (e4.y*invPi1)*unpack_sum(a1))
                        + ((e4.z*invPi2)*unpack_sum(a2) + (e4.w*invPi3)*unpack_sum(a3));
                s += __shfl_xor_sync(0xffffffffu, s, 1);
                s += __shfl_xor_sync(0xffffffffu, s, 2);
                accll[t] += 0.25f * (__log2f(s) + sNuL[mu*NG + g]);
            }
        }

        // ---- Deterministic per-g reduction over the 16 threads sharing g ----
        sacc0[tid] = accll[0];
        sacc1[tid] = accll[1];
        __syncthreads();
        if (tid < NG) {
            float s0 = 0.f, s1 = 0.f;
            #pragma unroll
            for (int kk = 0; kk < 16; kk++) {
                int src = (kk >> 2)*64 + tid*4 + (kk & 3);
                s0 += sacc0[src];
                s1 += sacc1[src];
            }
            // 127 internal nodes owe -1 each in log2 (folded BF=2 mean); to ln
            out[(2*pair    )*NG + tid] = 0.69314718055994530942f * (s0 - 127.0f);
            out[(2*pair + 1)*NG + tid] = 0.69314718055994530942f * (s1 - 127.0f);
        }
    }
}

// ---------------------------------------------------------------------------
extern "C" void kernel_launch(void* const* d_in, const int* in_sizes, int n_in,
                              void* d_out, int out_size) {
    const float* A  = (const float*)d_in[0];
    const float* B  = (const float*)d_in[1];
    const float* Pi = (const float*)d_in[2];
    const int*   x  = (const int*)  d_in[3];
    float* out = (float*)d_out;

    cudaFuncSetAttribute(htmm_upward_kernel,
                         cudaFuncAttributeMaxDynamicSharedMemorySize, DYN_BYTES);

    htmm_softmax_kernel<<<1, 256>>>(A, B, Pi);
    htmm_upward_kernel<<<PGRID, 256, DYN_BYTES>>>(x, out);
}

// round 10
// speedup vs baseline: 1.1324x; 1.1324x over previous
#include <cuda_runtime.h>
#include <math.h>

#define NT 2000
#define NPT 255
#define NC 16
#define NM 32
#define NG 16
#define PGRID 296                     // persistent grid: 2 CTAs/SM x 148 SMs

typedef unsigned long long ull;

// dynamic shared layout (float offsets) — R8 sizes
#define W_FLOATS (32*256)             // 32KB: pairsum slots; subtree ng owns [ng*8, ng*8+8)
#define BF_FLOATS (NM*NG*NC)          // 32KB: emission table [m][g][c]
#define PB_FLOATS (NM*NG*NC)          // 32KB: normalized leaf beta Pi*B/nu, [m][g][c]
#define DYN_FLOATS (W_FLOATS + BF_FLOATS + PB_FLOATS + NM*NG)
#define DYN_BYTES  (DYN_FLOATS*4)     // 100352 B -> 2 CTAs/SM

__device__ float g_smA[NC*NC*NG];     // softmaxed A, [p][c][g]
__device__ float g_smBf[NM*NG*NC];    // softmaxed B, [m][g][c]
__device__ float g_smPi[NC*NG];       // softmaxed Pi, [c][g]
__device__ float g_PiBn[NM*NG*NC];    // normalized leaf beta, [m][g][c]
__device__ float g_nuLog[NM*NG];      // log2 nu per (m,g)

// ---------------------------------------------------------------------------
// packed f32x2 helpers (FFMA2/FADD2 only reachable via PTX)
// ---------------------------------------------------------------------------
__device__ __forceinline__ ull pack2(float lo, float hi) {
    ull r; asm("mov.b64 %0, {%1, %2};" : "=l"(r) : "f"(lo), "f"(hi)); return r;
}
__device__ __forceinline__ void ffma2(ull& d, ull a, ull b) {
    asm("fma.rn.f32x2 %0, %1, %2, %0;" : "+l"(d) : "l"(a), "l"(b));
}
__device__ __forceinline__ void fadd2(ull& d, ull a) {
    asm("add.rn.f32x2 %0, %0, %1;" : "+l"(d) : "l"(a));
}
__device__ __forceinline__ float unpack_sum(ull v) {
    float lo, hi; asm("mov.b64 {%0, %1}, %2;" : "=f"(lo), "=f"(hi) : "l"(v));
    return lo + hi;
}

// ---------------------------------------------------------------------------
// Prologue: softmaxes + emission table + normalized leaf table + log2 nu.
// ---------------------------------------------------------------------------
__global__ void htmm_softmax_kernel(const float* __restrict__ A,
                                    const float* __restrict__ B,
                                    const float* __restrict__ Pi) {
    int tid = threadIdx.x;
    int c = tid >> 4;
    int g = tid & 15;
    {   // A: softmax over p for each (c,g)
        float mx = -1e30f;
        #pragma unroll
        for (int p = 0; p < NC; p++) mx = fmaxf(mx, A[p*NC*NG + c*NG + g]);
        float e[NC]; float s = 0.f;
        #pragma unroll
        for (int p = 0; p < NC; p++) { e[p] = expf(A[p*NC*NG + c*NG + g] - mx); s += e[p]; }
        float rs = 1.f / s;
        #pragma unroll
        for (int p = 0; p < NC; p++) g_smA[p*NC*NG + c*NG + g] = e[p] * rs;
    }
    {   // B: softmax over m for each (c,g); store [m][g][c]
        float mx = -1e30f;
        #pragma unroll
        for (int m = 0; m < NM; m++) mx = fmaxf(mx, B[c*NM*NG + m*NG + g]);
        float s = 0.f;
        #pragma unroll
        for (int m = 0; m < NM; m++) s += expf(B[c*NM*NG + m*NG + g] - mx);
        float rs = 1.f / s;
        #pragma unroll
        for (int m = 0; m < NM; m++)
            g_smBf[m*NG*NC + g*NC + c] = expf(B[c*NM*NG + m*NG + g] - mx) * rs;
    }
    if (tid < NG) {   // Pi: softmax over c for each g
        int gg = tid;
        float mx = -1e30f;
        #pragma unroll
        for (int cc = 0; cc < NC; cc++) mx = fmaxf(mx, Pi[cc*NG + gg]);
        float s = 0.f;
        #pragma unroll
        for (int cc = 0; cc < NC; cc++) s += expf(Pi[cc*NG + gg] - mx);
        float rs = 1.f / s;
        #pragma unroll
        for (int cc = 0; cc < NC; cc++)
            g_smPi[cc*NG + gg] = expf(Pi[cc*NG + gg] - mx) * rs;
    }
    __syncthreads();
    // per (m,g): v = Pi*B; nu = sum v; PiBn = v/nu; log2 nu
    for (int i = tid; i < NM*NG; i += 256) {
        int m = i >> 4, gg = i & 15;
        float v[NC]; float nu = 0.f;
        #pragma unroll
        for (int cc = 0; cc < NC; cc++) {
            v[cc] = g_smPi[cc*NG + gg] * g_smBf[m*NG*NC + gg*NC + cc];
            nu += v[cc];
        }
        float rnu = 1.f / nu;
        #pragma unroll
        for (int cc = 0; cc < NC; cc++)
            g_PiBn[m*NG*NC + gg*NC + cc] = v[cc] * rnu;
        g_nuLog[i] = log2f(nu);
    }
}

// ---------------------------------------------------------------------------
// Main kernel: PERSISTENT, SUBTREE-DECOMPOSED.
// ng = tid>>6 owns the subtree rooted at L2-node ng (1+2+4+8+16 nodes + 32
// leaves). Levels 6..2 of each subtree run with NO barriers (each ng touches
// only its own 8 w-slots; rows are per-g; quad read->shfl->write ordering).
// One barrier before L1/root (cross-subtree combine on ng0), one after sacc.
// pblk = tid&3 (states p = 4*pblk..+3), g = (tid>>2)&15.
// ---------------------------------------------------------------------------
__global__ void __launch_bounds__(256, 2)
htmm_upward_kernel(const int* __restrict__ x, float* __restrict__ out) {
    extern __shared__ __align__(16) float sm[];
    float* sW   = sm;                                   // 32 slots x 256 floats
    float* sBf  = sm + W_FLOATS;                        // [m][g][c]
    float* sPB  = sm + W_FLOATS + BF_FLOATS;            // [m][g][c]
    float* sNuL = sm + W_FLOATS + BF_FLOATS + PB_FLOATS;// [m*NG+g]
    __shared__ int   sx[NPT];
    __shared__ float sacc[256];

    const int tid  = threadIdx.x;
    const int pblk = tid & 3;
    const int g    = (tid >> 2) & 15;
    const int ng   = tid >> 6;
    const int rowoff = g*16;
    const int sbase  = ng*8;                            // this subtree's slot base

    // ---- stage tables ONCE (A via sW scratch; consumed into regs) ----
    for (int i = tid; i < NC*NC*NG; i += 256) sW[i]  = g_smA[i];
    for (int i = tid; i < BF_FLOATS; i += 256) sBf[i] = g_smBf[i];
    for (int i = tid; i < PB_FLOATS; i += 256) sPB[i] = g_PiBn[i];
    for (int i = tid; i < NM*NG; i += 256)     sNuL[i] = g_nuLog[i];
    __syncthreads();

    // A packed along c-pairs for this thread's states p = 4*pblk+ip
    ull A2[4][8];
    #pragma unroll
    for (int ip = 0; ip < 4; ip++) {
        int p = 4*pblk + ip;
        #pragma unroll
        for (int c2 = 0; c2 < 8; c2++)
            A2[ip][c2] = pack2(sW[p*256 + (2*c2)*16 + g],
                               sW[p*256 + (2*c2+1)*16 + g]);
    }

    // ---- persistent tree loop ----
    for (int tree = blockIdx.x; tree < NT; tree += PGRID) {
        __syncthreads();   // sW scratch (first iter) / previous tree done
        for (int i = tid; i < NPT; i += 256) sx[i] = x[tree*NPT + i];
        __syncthreads();

        float accll = 0.f;   // log2 units

        // ====== SUBTREE ng: levels 6..2, barrier-free ======

        // ---- Level 6 (leaves fused): 8 local parents k -> slots sbase+k ----
        for (int k = 0; k < 8; k++) {
            float wo0 = 0.f, wo1 = 0.f, wo2 = 0.f, wo3 = 0.f;
            #pragma unroll
            for (int sel = 0; sel < 2; sel++) {
                const int j  = 2*k + sel;                   // local L6 node 0..15
                const int lf = 127 + 32*ng + 2*j;
                const int m0 = sx[lf], m1 = sx[lf + 1];
                const ull* b0 = (const ull*)(sPB + m0*256 + rowoff);
                const ull* b1 = (const ull*)(sPB + m1*256 + rowoff);
                ull a0 = 0ull, a1 = 0ull, a2 = 0ull, a3 = 0ull;
                #pragma unroll
                for (int c2 = 0; c2 < 8; c2++) {
                    ull w = b0[c2];
                    fadd2(w, b1[c2]);            // beta_leaf0 + beta_leaf1 (exact)
                    ffma2(a0, A2[0][c2], w);
                    ffma2(a1, A2[1][c2], w);
                    ffma2(a2, A2[2][c2], w);
                    ffma2(a3, A2[3][c2], w);
                }
                accll += 0.25f * (sNuL[m0*NG + g] + sNuL[m1*NG + g]);  // leaf lls

                const int mu = sx[63 + 16*ng + j];
                const float4 e4 = *(const float4*)(sBf + mu*256 + rowoff + 4*pblk);
                float bv0 = e4.x * unpack_sum(a0);
                float bv1 = e4.y * unpack_sum(a1);
                float bv2 = e4.z * unpack_sum(a2);
                float bv3 = e4.w * unpack_sum(a3);
                float s = (bv0 + bv1) + (bv2 + bv3);
                s += __shfl_xor_sync(0xffffffffu, s, 1);
                s += __shfl_xor_sync(0xffffffffu, s, 2);
                float rs = __fdividef(1.f, s);
                wo0 += bv0*rs; wo1 += bv1*rs; wo2 += bv2*rs; wo3 += bv3*rs;
                accll += 0.25f * __log2f(s);
            }
            *(float4*)(sW + (sbase + k)*256 + rowoff + 4*pblk) =
                make_float4(wo0, wo1, wo2, wo3);
        }

        // ---- Levels 5..3 (in-place, stride doubling, local to subtree) ----
        #pragma unroll 1
        for (int l = 5; l >= 3; l--) {
            const int nParL = 1 << (l - 3);          // 4, 2, 1
            const int st    = 1 << (5 - l);          // 1, 2, 4
            const int nbase = (1 << l) - 1 + (1 << (l - 2))*ng;  // global node base
            for (int k = 0; k < nParL; k++) {
                float wo0 = 0.f, wo1 = 0.f, wo2 = 0.f, wo3 = 0.f;
                #pragma unroll
                for (int sel = 0; sel < 2; sel++) {
                    const int j = 2*k + sel;
                    const ull* wv = (const ull*)(sW + (sbase + j*st)*256 + rowoff);
                    ull a0 = 0ull, a1 = 0ull, a2 = 0ull, a3 = 0ull;
                    #pragma unroll
                    for (int c2 = 0; c2 < 8; c2++) {
                        ull w = wv[c2];                  // pre-summed sibling pair
                        ffma2(a0, A2[0][c2], w);
                        ffma2(a1, A2[1][c2], w);
                        ffma2(a2, A2[2][c2], w);
                        ffma2(a3, A2[3][c2], w);
                    }
                    const int mu = sx[nbase + j];
                    const float4 e4 = *(const float4*)(sBf + mu*256 + rowoff + 4*pblk);
                    float bv0 = e4.x * unpack_sum(a0);
                    float bv1 = e4.y * unpack_sum(a1);
                    float bv2 = e4.z * unpack_sum(a2);
                    float bv3 = e4.w * unpack_sum(a3);
                    float s = (bv0 + bv1) + (bv2 + bv3);
                    s += __shfl_xor_sync(0xffffffffu, s, 1);
                    s += __shfl_xor_sync(0xffffffffu, s, 2);
                    // true nu = s/2; /2 cancels in normalization, -1 folded at end
                    float rs = __fdividef(1.f, s);
                    wo0 += bv0*rs; wo1 += bv1*rs; wo2 += bv2*rs; wo3 += bv3*rs;
                    accll += 0.25f * __log2f(s);
                }
                *(float4*)(sW + (sbase + 2*k*st)*256 + rowoff + 4*pblk) =
                    make_float4(wo0, wo1, wo2, wo3);
            }
        }

        // ---- L2 node (one per subtree): normalized beta -> slot sbase+1 ----
        {
            const ull* wv = (const ull*)(sW + sbase*256 + rowoff);  // L3 pairsum
            ull a0 = 0ull, a1 = 0ull, a2 = 0ull, a3 = 0ull;
            #pragma unroll
            for (int c2 = 0; c2 < 8; c2++) {
                ull w = wv[c2];
                ffma2(a0, A2[0][c2], w);
                ffma2(a1, A2[1][c2], w);
                ffma2(a2, A2[2][c2], w);
                ffma2(a3, A2[3][c2], w);
            }
            const int mu = sx[3 + ng];
            const float4 e4 = *(const float4*)(sBf + mu*256 + rowoff + 4*pblk);
            float bv0 = e4.x * unpack_sum(a0);
            float bv1 = e4.y * unpack_sum(a1);
            float bv2 = e4.z * unpack_sum(a2);
            float bv3 = e4.w * unpack_sum(a3);
            float s = (bv0 + bv1) + (bv2 + bv3);
            s += __shfl_xor_sync(0xffffffffu, s, 1);
            s += __shfl_xor_sync(0xffffffffu, s, 2);
            float rs = __fdividef(1.f, s);
            *(float4*)(sW + (sbase + 1)*256 + rowoff + 4*pblk) =
                make_float4(bv0*rs, bv1*rs, bv2*rs, bv3*rs);
            accll += 0.25f * __log2f(s);
        }

        __syncthreads();   // L2 betas of all 4 subtrees visible

        // ---- L1 + root: ng0 only ----
        if (ng == 0) {
            float wo0 = 0.f, wo1 = 0.f, wo2 = 0.f, wo3 = 0.f;
            #pragma unroll
            for (int sel = 0; sel < 2; sel++) {
                const ull* r0 = (const ull*)(sW + (2*sel*8 + 1)*256 + rowoff);
                const ull* r1 = (const ull*)(sW + ((2*sel+1)*8 + 1)*256 + rowoff);
                ull a0 = 0ull, a1 = 0ull, a2 = 0ull, a3 = 0ull;
                #pragma unroll
                for (int c2 = 0; c2 < 8; c2++) {
                    ull w = r0[c2];
                    fadd2(w, r1[c2]);                    // beta_L2 pairsum
                    ffma2(a0, A2[0][c2], w);
                    ffma2(a1, A2[1][c2], w);
                    ffma2(a2, A2[2][c2], w);
                    ffma2(a3, A2[3][c2], w);
                }
                const int mu = sx[1 + sel];
                const float4 e4 = *(const float4*)(sBf + mu*256 + rowoff + 4*pblk);
                float bv0 = e4.x * unpack_sum(a0);
                float bv1 = e4.y * unpack_sum(a1);
                float bv2 = e4.z * unpack_sum(a2);
                float bv3 = e4.w * unpack_sum(a3);
                float s = (bv0 + bv1) + (bv2 + bv3);
                s += __shfl_xor_sync(0xffffffffu, s, 1);
                s += __shfl_xor_sync(0xffffffffu, s, 2);
                float rs = __fdividef(1.f, s);
                wo0 += bv0*rs; wo1 += bv1*rs; wo2 += bv2*rs; wo3 += bv3*rs;
                accll += 0.25f * __log2f(s);
            }
            // stage L1 pairsum through slot 2, then root
            *(float4*)(sW + 2*256 + rowoff + 4*pblk) =
                make_float4(wo0, wo1, wo2, wo3);
            __syncwarp();
            const ull* wv = (const ull*)(sW + 2*256 + rowoff);
            ull a0 = 0ull, a1 = 0ull, a2 = 0ull, a3 = 0ull;
            #pragma unroll
            for (int c2 = 0; c2 < 8; c2++) {
                ull w = wv[c2];
                ffma2(a0, A2[0][c2], w);
                ffma2(a1, A2[1][c2], w);
                ffma2(a2, A2[2][c2], w);
                ffma2(a3, A2[3][c2], w);
            }
            const int mu = sx[0];
            const float4 e4 = *(const float4*)(sBf + mu*256 + rowoff + 4*pblk);
            float s = (e4.x*unpack_sum(a0) + e4.y*unpack_sum(a1))
                    + (e4.z*unpack_sum(a2) + e4.w*unpack_sum(a3));
            s += __shfl_xor_sync(0xffffffffu, s, 1);
            s += __shfl_xor_sync(0xffffffffu, s, 2);
            accll += 0.25f * __log2f(s);
        }

        // ---- Deterministic per-g reduction over the 16 threads sharing g ----
        sacc[tid] = accll;
        __syncthreads();
        if (tid < NG) {
            float s = 0.f;
            #pragma unroll
            for (int kk = 0; kk < 16; kk++)
                s += sacc[(kk >> 2)*64 + tid*4 + (kk & 3)];
            // 127 internal nodes owe -1 each in log2 (folded BF=2 mean); to ln
            out[tree*NG + tid] = 0.69314718055994530942f * (s - 127.0f);
        }
    }
}

// ---------------------------------------------------------------------------
extern "C" void kernel_launch(void* const* d_in, const int* in_sizes, int n_in,
                              void* d_out, int out_size) {
    const float* A  = (const float*)d_in[0];
    const float* B  = (const float*)d_in[1];
    const float* Pi = (const float*)d_in[2];
    const int*   x  = (const int*)  d_in[3];
    float* out = (float*)d_out;

    cudaFuncSetAttribute(htmm_upward_kernel,
                         cudaFuncAttributeMaxDynamicSharedMemorySize, DYN_BYTES);

    htmm_softmax_kernel<<<1, 256>>>(A, B, Pi);
    htmm_upward_kernel<<<PGRID, 256, DYN_BYTES>>>(x, out);
}